// round 13
// baseline (speedup 1.0000x reference)
#include <cuda_runtime.h>
#include <math.h>

#define Bn 8
#define Cn 64
#define Ln 2048
#define SL (Bn*Cn*Ln)
#define NT (4*SL)
#define TLX 128
#define SW 148
#define BW 146

__device__ float g_coef[NT];
__device__ float g_y[NT];
__device__ float g_y2[NT];
__device__ float g_bufA[SL];
__device__ float g_bufB[SL];

__device__ float    g_stat[Bn*Cn];
__device__ float    g_lo[Bn*7];
__device__ float    g_hi[Bn*7];
__device__ float    g_sumP[16];
__device__ unsigned g_mnB[4];
__device__ unsigned g_mxB[4];
__device__ unsigned g_maxS[4];
__device__ float    g_ts[20];
__device__ float    g_dt[16];
__device__ float    g_G[64*128];
__device__ float    g_w1T[4*192*64];
__device__ float    g_w2T[4*192*64];
__device__ float    g_wgT[3*192*64];
__device__ float    g_ein[32];
__device__ float    g_eout[32];
__device__ float    g_scale[32];
__device__ float    g_dummy[4];

__device__ __forceinline__ float geluf(float x){ return 0.5f*x*(1.0f+erff(x*0.70710678118654752f)); }
__device__ __forceinline__ float siluf(float x){ return x/(1.0f+expf(-x)); }
__device__ __forceinline__ float sigmf(float x){ return 1.0f/(1.0f+expf(-x)); }

__global__ void k_reset(){
    int t=threadIdx.x;
    if(t<16){ g_sumP[t]=0.f; g_dt[t]=0.f; }
    if(t<4){ g_mnB[t]=0x7F800000u; g_mxB[t]=0u; g_maxS[t]=0u; }
    if(t<32){ g_ein[t]=0.f; g_eout[t]=0.f; }
}

__global__ void k_stat(const float* __restrict__ in){
    __shared__ float red[256];
    int row=blockIdx.x; const float* p=in+(size_t)row*Ln;
    float s=0.f;
    for(int i=threadIdx.x;i<Ln;i+=256) s+=p[i];
    red[threadIdx.x]=s; __syncthreads();
    for(int k=128;k;k>>=1){ if(threadIdx.x<k) red[threadIdx.x]+=red[threadIdx.x+k]; __syncthreads(); }
    if(!threadIdx.x) g_stat[row]=red[0]*(1.0f/Ln);
}

__global__ void k_dywan(const float* __restrict__ w1,const float* __restrict__ b1,
                        const float* __restrict__ wg1,const float* __restrict__ bg1,
                        const float* __restrict__ wg2,const float* __restrict__ bg2,
                        float* __restrict__ orthoOut){
    __shared__ float sh1[512];
    __shared__ float sh2[1024];
    __shared__ float shf[112];
    __shared__ float shinv[8];
    __shared__ float red[256];
    int t=threadIdx.x;
    for(int e=t;e<512;e+=256){
        int b=e>>6,o=e&63; float s=b1[o];
        const float* st=&g_stat[b*64];
        #pragma unroll 8
        for(int c=0;c<64;c++) s=fmaf(st[c],w1[o*64+c],s);
        sh1[e]=geluf(s);
    }
    __syncthreads();
    for(int e=t;e<1024;e+=256){
        int b=e>>7,o=e&127; float s=bg1[o];
        #pragma unroll 8
        for(int i=0;i<64;i++) s=fmaf(sh1[b*64+i],wg1[o*64+i],s);
        sh2[e]=geluf(s);
    }
    __syncthreads();
    if(t<112){
        int b=t/14, jj=t-b*14; float s=bg2[jj];
        #pragma unroll 8
        for(int i=0;i<128;i++) s=fmaf(sh2[b*128+i],wg2[jj*128+i],s);
        shf[t]=s;
        if(jj<7) g_lo[b*7+jj]=s; else g_hi[b*7+(jj-7)]=s;
    }
    __syncthreads();
    float contrib=0.f;
    if(t<8){
        float n2=0.f;
        #pragma unroll
        for(int i=0;i<7;i++){ float v=shf[t*14+i]; n2=fmaf(v,v,n2); }
        float inv=1.f/(sqrtf(n2)+1e-8f);
        shinv[t]=inv;
        contrib += fabsf(n2*inv*inv-1.f)*(0.01f*0.125f);
    }
    __syncthreads();
    if(t<64){
        int b=t>>3, j2=t&7;
        float cur=(j2<7)?shf[b*14+j2]:0.f;
        float prev=(j2>0)?shf[b*14+j2-1]:0.f;
        contrib += fabsf(cur-prev)*(0.1f/64.f);
    }
    for(int idx=t; idx<1176; idx+=256){
        int b=idx/147, r=idx-b*147;
        int s=r/49+1, ij=r-(s-1)*49;
        int i=ij/7, j=ij-7*i;
        float inv=shinv[b];
        float a=shf[b*14+i]*inv;
        float c=shf[b*14+((j-s+7)%7)]*inv;
        contrib += fabsf(a*c)*(0.01f/392.f);
    }
    for(int o=16;o;o>>=1) contrib+=__shfl_down_sync(0xffffffffu,contrib,o);
    if((t&31)==0) red[t>>5]=contrib;
    __syncthreads();
    if(t==0){
        float r=0.f;
        for(int i=0;i<8;i++) r+=red[i];
        orthoOut[0]=r;
    }
}

__global__ void k_wfilt(const float* __restrict__ in, float* __restrict__ outLo,
                        float* __restrict__ outHi, float* __restrict__ dupLo,
                        float* __restrict__ dupHi, int doStat){
    __shared__ float xr[Ln+6];
    __shared__ float red[256];
    int row=blockIdx.x, b=row>>6;
    const float* p=in+(size_t)row*Ln;
    for(int j=threadIdx.x;j<Ln+6;j+=256){
        int gg=j-3; gg=min(max(gg,0),Ln-1);
        xr[j]=p[gg];
    }
    float fl[7],fh[7];
    #pragma unroll
    for(int k=0;k<7;k++){ fl[k]=g_lo[b*7+k]; fh[k]=g_hi[b*7+k]; }
    __syncthreads();
    float s=0.f;
    for(int l=threadIdx.x;l<Ln;l+=256){
        float aL=0.f,aH=0.f;
        #pragma unroll
        for(int k=0;k<7;k++){ float v=xr[l+k]; aL=fmaf(v,fl[k],aL); aH=fmaf(v,fh[k],aH); }
        size_t g=(size_t)row*Ln+l;
        outLo[g]=aL;
        outHi[g]=aH;
        if(dupLo) dupLo[g]=aL;
        if(dupHi) dupHi[g]=aH;
        s+=aL;
    }
    if(doStat){
        red[threadIdx.x]=s; __syncthreads();
        for(int k=128;k;k>>=1){ if(threadIdx.x<k) red[threadIdx.x]+=red[threadIdx.x+k]; __syncthreads(); }
        if(!threadIdx.x) g_stat[row]=red[0]*(1.0f/Ln);
    }
}

__device__ __forceinline__ float brSum(float v, float* sh){
    for(int o=16;o;o>>=1) v+=__shfl_down_sync(0xffffffffu,v,o);
    if((threadIdx.x&31)==0) sh[threadIdx.x>>5]=v;
    __syncthreads();
    float r=0.f;
    if(threadIdx.x==0){ for(int i=0;i<8;i++) r+=sh[i]; }
    __syncthreads();
    return r;
}
__device__ __forceinline__ float brMin(float v, float* sh){
    for(int o=16;o;o>>=1) v=fminf(v,__shfl_down_sync(0xffffffffu,v,o));
    if((threadIdx.x&31)==0) sh[threadIdx.x>>5]=v;
    __syncthreads();
    float r=3.4e38f;
    if(threadIdx.x==0){ for(int i=0;i<8;i++) r=fminf(r,sh[i]); }
    __syncthreads();
    return r;
}
__device__ __forceinline__ float brMax(float v, float* sh){
    for(int o=16;o;o>>=1) v=fmaxf(v,__shfl_down_sync(0xffffffffu,v,o));
    if((threadIdx.x&31)==0) sh[threadIdx.x>>5]=v;
    __syncthreads();
    float r=0.f;
    if(threadIdx.x==0){ for(int i=0;i<8;i++) r=fmaxf(r,sh[i]); }
    __syncthreads();
    return r;
}

__global__ void k_tgrid(){
    __shared__ float xr[Ln];
    __shared__ float ga[Ln];
    __shared__ float sh[8];
    int row=blockIdx.x, lvl=blockIdx.y, t=threadIdx.x;
    const float* p=g_coef + (size_t)lvl*SL + (size_t)row*Ln;
    float e=0.f;
    for(int i=t;i<Ln;i+=256){ float v=p[i]; xr[i]=v; e=fmaf(v,v,e); }
    __syncthreads();
    for(int i=t;i<Ln-1;i+=256) ga[i]=fabsf(xr[i+1]-xr[i]);
    __syncthreads();
    float s0=0.f,s1=0.f,s2=0.f,s3=0.f,mn=3.4e38f,mx=0.f;
    for(int i=t;i<2047;i+=256){
        int a=i-2; if(a<0)a=0;
        int b=i+2; if(b>2046)b=2046;
        float v=0.f;
        for(int m=a;m<=b;m++) v+=ga[m];
        v*=0.2f;
        mn=fminf(mn,v); mx=fmaxf(mx,v);
        if(i<511)  s0+=v;
        if(i<1023) s1+=v;
        if(i<1534) s2+=v;
        if(i<2046) s3+=v;
    }
    float re=brSum(e,sh);
    float r0=brSum(s0,sh), r1=brSum(s1,sh), r2=brSum(s2,sh), r3=brSum(s3,sh);
    float rmn=brMin(mn,sh), rmx=brMax(mx,sh);
    if(t==0){
        atomicAdd(&g_ein[lvl*8+(row>>6)],re);
        atomicAdd(&g_sumP[lvl*4+0],r0);
        atomicAdd(&g_sumP[lvl*4+1],r1);
        atomicAdd(&g_sumP[lvl*4+2],r2);
        atomicAdd(&g_sumP[lvl*4+3],r3);
        atomicMin(&g_mnB[lvl],__float_as_uint(rmn));
        atomicMax(&g_mxB[lvl],__float_as_uint(rmx));
        atomicMax(&g_maxS[lvl],__float_as_uint(r3));
    }
}

__global__ void k_ts(){
    int lvl=threadIdx.x;
    if(lvl>=4) return;
    float mn=__uint_as_float(g_mnB[lvl]);
    float mx=__uint_as_float(g_mxB[lvl]);
    const int IDX[5]={0,511,1023,1534,2046};
    float ts[5]; ts[0]=0.f;
    float tgmax;
    if(mx-mn<1e-8f){
        for(int k=1;k<5;k++) ts[k]=0.5f*(float)IDX[k];
        tgmax=0.5f*2046.f;
    }else{
        float sc=0.9f/(mx-mn+1e-30f);
        for(int k=1;k<5;k++){
            float meanS=g_sumP[lvl*4+(k-1)]*(1.f/512.f);
            ts[k]=(float)IDX[k]*0.1f + sc*(meanS-(float)IDX[k]*mn);
        }
        float maxS=__uint_as_float(g_maxS[lvl]);
        tgmax=2046.f*0.1f + sc*(maxS-2046.f*mn);
    }
    tgmax=fmaxf(tgmax,1e-12f);
    float inv=1.f/tgmax;
    for(int k=0;k<5;k++){ ts[k]*=inv; g_ts[lvl*5+k]=ts[k]; }
    for(int j=0;j<4;j++) g_dt[lvl*4+j]=ts[j+1]-ts[j];
}

__global__ void k_modtab(const float* __restrict__ wt,const float* __restrict__ bt,
                         const float* __restrict__ wm,const float* __restrict__ bm,
                         const float* __restrict__ emb){
    for(int idx=threadIdx.x; idx<64*128; idx+=256){
        int combo=idx>>7, o=idx&127;
        int lvl=combo>>4, j=(combo>>2)&3, ev=combo&3;
        float t0=g_ts[lvl*5+j], t1=g_ts[lvl*5+j+1];
        float tt=(ev==0)?t0:((ev==3)?t1:(t0+0.5f*(t1-t0)));
        float s=bm[lvl*128+o];
        #pragma unroll
        for(int d=0;d<16;d++){
            float te=wt[lvl*16+d]*tt+bt[lvl*16+d];
            te=siluf(te);
            s=fmaf(wm[(lvl*128+o)*16+d],te,s);
        }
        if(o<64) g_G[combo*128+o]=1.f+s+emb[(lvl*8+lvl)*64+o];
        else     g_G[combo*128+o]=s;
    }
}

__global__ void k_wprep(const float* __restrict__ c1,const float* __restrict__ c2,
                        const float* __restrict__ gw){
    int i=blockIdx.x*256+threadIdx.x;
    if(i<4*12288){
        int lvl=i/12288, r=i-lvl*12288, ck=r>>6, o=r&63, c=ck/3, k=ck-3*c;
        int src=lvl*12288+o*192+c*3+k;
        g_w1T[i]=c1[src];
        g_w2T[i]=c2[src];
        if(lvl<3) g_wgT[i]=gw[src];
    }
}

/* conv stage inside fused RK; each warp computes 9 columns [cb,cb+9) for
   output channels (lane, lane+32). Written region per block: cols [1,145).
   ACT 0: dst=mask*gelu(conv+bias)
   ACT 1: dst=mask*(silu((conv+bias)*ga+be)-0.1*dst)  (dst held in_e) */
template<int ACT>
__device__ __forceinline__ void conv_stage(const float* src, float* dst,
    const float* wT, const float* bias, const float* ga, const float* be,
    int cb, int lane, int l0)
{
    float a0[9],a1[9];
    #pragma unroll
    for(int p=0;p<9;p++){a0[p]=0.f;a1[p]=0.f;}

    for(int c=0;c<64;c++){
        float xv[11];
        #pragma unroll
        for(int i=0;i<11;i++) xv[i]=src[c*SW+cb-1+i];
        const float* wp=wT+c*192;
        float w00=__ldg(wp+lane),     w01=__ldg(wp+64+lane),  w02=__ldg(wp+128+lane);
        float w10=__ldg(wp+32+lane),  w11=__ldg(wp+96+lane),  w12=__ldg(wp+160+lane);
        #pragma unroll
        for(int p=0;p<9;p++){
            a0[p]=fmaf(xv[p],w00,fmaf(xv[p+1],w01,fmaf(xv[p+2],w02,a0[p])));
            a1[p]=fmaf(xv[p],w10,fmaf(xv[p+1],w11,fmaf(xv[p+2],w12,a1[p])));
        }
    }

    float b0=bias[lane], b1=bias[lane+32];
    float g0=0.f,g1=0.f,bb0=0.f,bb1=0.f;
    if(ACT==1){ g0=ga[lane]; g1=ga[lane+32]; bb0=be[lane]; bb1=be[lane+32]; }

    #pragma unroll
    for(int p=0;p<9;p++){
        int cc=cb+p;
        int g=l0-9+cc;
        bool inr=(g>=0)&&(g<Ln);
        int ad0=lane*SW+cc, ad1=(lane+32)*SW+cc;
        if(ACT==0){
            dst[ad0]=inr?geluf(a0[p]+b0):0.f;
            dst[ad1]=inr?geluf(a1[p]+b1):0.f;
        }else{
            float y0=dst[ad0], y1=dst[ad1];
            float m0=fmaf(a0[p]+b0,g0,bb0);
            float m1=fmaf(a1[p]+b1,g1,bb1);
            dst[ad0]=inr?(siluf(m0)-0.1f*y0):0.f;
            dst[ad1]=inr?(siluf(m1)-0.1f*y1):0.f;
        }
    }
}

/* fused RK4 step, 512 threads (16 warps, 9 cols each); j==3 adds e_out */
__global__ void __launch_bounds__(512,2) k_rk(
    const float* __restrict__ yIn, float* __restrict__ yOut,
    const float* __restrict__ b1All, const float* __restrict__ b2All, int j)
{
    extern __shared__ float smx[];
    float* A  = smx;
    float* Bf = smx + 64*SW;
    __shared__ float redE[16];
    int t=threadIdx.x, lane=t&31, w=t>>5;   /* w in [0,16) */
    int slab=blockIdx.y, lvl=slab>>3;
    size_t soff=(size_t)slab*(Cn*Ln);
    int l0=blockIdx.x*TLX;
    int cb=1+9*w;                            /* cols [1,145) covered */

    float dt=g_dt[lvl*4+j];
    const float* w1T=g_w1T+lvl*12288;
    const float* w2T=g_w2T+lvl*12288;
    const float* bias1=b1All+lvl*64;
    const float* bias2=b2All+lvl*64;
    const float* yS=yIn+soff;

    float acc[16];
    #pragma unroll
    for(int i=0;i<16;i++) acc[i]=0.f;

    for(int idx=t; idx<64*BW; idx+=512){
        int c=idx/BW, b=idx-c*BW;
        int g=l0-9+b;
        A[c*SW+b]=(g>=0&&g<Ln)? yS[(size_t)c*Ln+g] : 0.f;
    }
    for(int idx=t; idx<128; idx+=512){
        int c=idx>>1, col=(idx&1)?(BW-1):0;
        Bf[c*SW+col]=0.f;
    }
    __syncthreads();

    for(int ev=0; ev<4; ev++){
        float* inB=(ev&1)?Bf:A;
        float* hB =(ev&1)?A:Bf;
        float kcoef=(ev==1||ev==2)?2.f:1.f;

        conv_stage<0>(inB,hB,w1T,bias1,(const float*)0,(const float*)0,cb,lane,l0);
        __syncthreads();
        const float* Gp=g_G+((lvl*4+j)*4+ev)*128;
        conv_stage<1>(hB,inB,w2T,bias2,Gp,Gp+64,cb,lane,l0);
        __syncthreads();

        float* kB=inB;
        #pragma unroll
        for(int i=0;i<16;i++){
            int idx=t+i*512;
            int c=idx>>7, l=idx&127;
            acc[i]=fmaf(kcoef,kB[c*SW+l+9],acc[i]);
        }
        if(ev<3){
            float aN=(ev==2)?dt:0.5f*dt;
            for(int idx=t; idx<64*BW; idx+=512){
                int c=idx/BW, b=idx-c*BW;
                int g=l0-9+b;
                float v=0.f;
                if(g>=0&&g<Ln) v=fmaf(aN,kB[c*SW+b],yS[(size_t)c*Ln+g]);
                hB[c*SW+b]=v;
            }
        }
        __syncthreads();
    }

    float s6=dt*(1.f/6.f);
    float esum=0.f;
    #pragma unroll
    for(int i=0;i<16;i++){
        int idx=t+i*512;
        int c=idx>>7, l=idx&127;
        size_t g=soff+(size_t)c*Ln+l0+l;
        float yv=fmaf(s6,acc[i],yIn[g]);
        yOut[g]=yv;
        esum=fmaf(yv,yv,esum);
    }
    if(j==3){
        for(int o=16;o;o>>=1) esum+=__shfl_down_sync(0xffffffffu,esum,o);
        if(lane==0) redE[w]=esum;
        __syncthreads();
        if(t==0){
            float r=0.f;
            for(int i=0;i<16;i++) r+=redE[i];
            atomicAdd(&g_eout[slab],r);
        }
    }
}

__global__ void k_sc(){
    int i=threadIdx.x;
    if(i<32){
        float einm =g_ein[i]*(1.f/(float)(Cn*Ln));
        float eoutm=g_eout[i]*(1.f/(float)(Cn*Ln));
        g_scale[i]=sqrtf(einm/(eoutm+1e-8f));
    }
}

__global__ void __launch_bounds__(256) k_gate(
    const float* __restrict__ cur, const float* __restrict__ bAll,
    const float* __restrict__ det, float* __restrict__ outp, int gi,
    int curBase, int detBase, float* __restrict__ detCopy)
{
    __shared__ float xs[64*130];
    int t=threadIdx.x;
    int slab=blockIdx.y;
    size_t soff=(size_t)slab*(Cn*Ln);
    int l0=blockIdx.x*TLX;
    const float* wT=g_wgT+gi*12288;
    const float* ip=cur+soff;
    float sc=(curBase>=0)?g_scale[curBase+slab]:1.f;
    float sd=(detBase>=0)?g_scale[detBase+slab]:1.f;

    for(int idx=t; idx<64*130; idx+=256){
        int c=idx/130, jj=idx-130*c;
        int gl=l0-1+jj;
        xs[idx]=(gl>=0&&gl<Ln)? ip[(size_t)c*Ln+gl]*sc : 0.f;
    }
    __syncthreads();

    int lane=t&31, w=t>>5;
    int base=w*16;
    float acc0[16],acc1[16];
    #pragma unroll
    for(int i=0;i<16;i++){acc0[i]=0.f;acc1[i]=0.f;}

    for(int c=0;c<64;c++){
        float xv[18];
        #pragma unroll
        for(int i2=0;i2<18;i2++) xv[i2]=xs[c*130+base+i2];
        const float* wp=wT+c*192;
        float w00=__ldg(wp+lane),     w01=__ldg(wp+64+lane),  w02=__ldg(wp+128+lane);
        float w10=__ldg(wp+32+lane),  w11=__ldg(wp+96+lane),  w12=__ldg(wp+160+lane);
        #pragma unroll
        for(int i2=0;i2<16;i2++){
            acc0[i2]=fmaf(xv[i2],w00,fmaf(xv[i2+1],w01,fmaf(xv[i2+2],w02,acc0[i2])));
            acc1[i2]=fmaf(xv[i2],w10,fmaf(xv[i2+1],w11,fmaf(xv[i2+2],w12,acc1[i2])));
        }
    }
    __syncthreads();
    #pragma unroll
    for(int i2=0;i2<16;i2++){
        xs[lane*130+base+i2]=acc0[i2];
        xs[(lane+32)*130+base+i2]=acc1[i2];
    }
    __syncthreads();

    const float* bptr=bAll+gi*64;
    for(int idx=t; idx<64*TLX; idx+=256){
        int c=idx>>7, l=idx&127;
        float v=xs[c*130+l]+bptr[c];
        size_t g=soff+(size_t)c*Ln+l0+l;
        float gt=sigmf(v);
        float dv=det[g]*sd;
        outp[g]=fmaf(gt,dv,cur[g]*sc);
        if(detCopy) detCopy[g]=dv;
    }
}

__global__ void k_attn(const float* __restrict__ cur, const float* __restrict__ det,
                       float* __restrict__ out, const float* __restrict__ w1,
                       const float* __restrict__ b1, const float* __restrict__ w2,
                       const float* __restrict__ b2, int detBase){
    int b=blockIdx.y;
    int l=blockIdx.x*128+threadIdx.x;
    size_t base=(size_t)b*(Cn*Ln)+l;
    float sd=g_scale[detBase+b];
    float h[16];
    #pragma unroll
    for(int i=0;i<16;i++) h[i]=b1[i];
    for(int c=0;c<64;c++){
        float v=cur[base+(size_t)c*Ln];
        #pragma unroll
        for(int i=0;i<16;i++) h[i]=fmaf(v,__ldg(w1+i*64+c),h[i]);
    }
    #pragma unroll
    for(int i=0;i<16;i++) h[i]=geluf(h[i]);
    for(int o=0;o<64;o++){
        float s=b2[o];
        #pragma unroll
        for(int i=0;i<16;i++) s=fmaf(h[i],__ldg(w2+o*16+i),s);
        float a=sigmf(s);
        size_t g=base+(size_t)o*Ln;
        out[g]=det[g]*sd*(1.f+a);
    }
}

extern "C" void kernel_launch(void* const* d_in, const int* in_sizes, int n_in,
                              void* d_out, int out_size){
    const float* x       =(const float*)d_in[0];
    const float* dy_w1   =(const float*)d_in[1];
    const float* dy_b1   =(const float*)d_in[2];
    const float* dy_wg1  =(const float*)d_in[3];
    const float* dy_bg1  =(const float*)d_in[4];
    const float* dy_wg2  =(const float*)d_in[5];
    const float* dy_bg2  =(const float*)d_in[6];
    const float* ode_c1w =(const float*)d_in[7];
    const float* ode_c1b =(const float*)d_in[8];
    const float* ode_c2w =(const float*)d_in[9];
    const float* ode_c2b =(const float*)d_in[10];
    const float* ode_wt  =(const float*)d_in[11];
    const float* ode_bt  =(const float*)d_in[12];
    const float* ode_wm  =(const float*)d_in[13];
    const float* ode_bm  =(const float*)d_in[14];
    const float* ode_emb =(const float*)d_in[15];
    const float* gate_w  =(const float*)d_in[16];
    const float* gate_b  =(const float*)d_in[17];
    const float* attn1_w =(const float*)d_in[18];
    const float* attn1_b =(const float*)d_in[19];
    const float* attn2_w =(const float*)d_in[20];
    const float* attn2_b =(const float*)d_in[21];
    float* out=(float*)d_out;

    void *vp;
    cudaGetSymbolAddress(&vp,g_coef);  float* pCoef=(float*)vp;
    cudaGetSymbolAddress(&vp,g_y);     float* pY   =(float*)vp;
    cudaGetSymbolAddress(&vp,g_y2);    float* pY2  =(float*)vp;
    cudaGetSymbolAddress(&vp,g_bufA);  float* pA   =(float*)vp;
    cudaGetSymbolAddress(&vp,g_bufB);  float* pB   =(float*)vp;
    cudaGetSymbolAddress(&vp,g_dummy); float* pDum =(float*)vp;

    float* orthoPtr=(out_size>NT)?(out+NT):pDum;

    const int shz = 2*64*SW*(int)sizeof(float);   /* 75776 B */
    cudaFuncSetAttribute(k_rk, cudaFuncAttributeMaxDynamicSharedMemorySize, shz);

    k_reset<<<1,32>>>();
    k_wprep<<<192,256>>>(ode_c1w,ode_c2w,gate_w);
    k_stat<<<512,256>>>(x);
    k_dywan<<<1,256>>>(dy_w1,dy_b1,dy_wg1,dy_bg1,dy_wg2,dy_bg2,orthoPtr);
    k_wfilt<<<512,256>>>(x,  pA, pCoef+1*SL, (float*)0, pY+1*SL, 1);
    k_dywan<<<1,256>>>(dy_w1,dy_b1,dy_wg1,dy_bg1,dy_wg2,dy_bg2,orthoPtr);
    k_wfilt<<<512,256>>>(pA, pB, pCoef+2*SL, (float*)0, pY+2*SL, 1);
    k_dywan<<<1,256>>>(dy_w1,dy_b1,dy_wg1,dy_bg1,dy_wg2,dy_bg2,orthoPtr);
    k_wfilt<<<512,256>>>(pB, pCoef, pCoef+3*SL, pY, pY+3*SL, 0);

    k_tgrid<<<dim3(512,4),256>>>();
    k_ts<<<1,32>>>();
    k_modtab<<<1,256>>>(ode_wt,ode_bt,ode_wm,ode_bm,ode_emb);

    /* fused RK4: y ping-pongs y <-> y2, ends in y; j=3 accumulates e_out */
    k_rk<<<dim3(16,32),512,shz>>>(pY,  pY2, ode_c1b, ode_c2b, 0);
    k_rk<<<dim3(16,32),512,shz>>>(pY2, pY,  ode_c1b, ode_c2b, 1);
    k_rk<<<dim3(16,32),512,shz>>>(pY,  pY2, ode_c1b, ode_c2b, 2);
    k_rk<<<dim3(16,32),512,shz>>>(pY2, pY,  ode_c1b, ode_c2b, 3);

    k_sc<<<1,32>>>();

    k_gate<<<dim3(16,8),256>>>(pY, gate_b, pY+3*SL, pA, 2, 0, 24, out+3*SL);
    k_attn<<<dim3(16,8),128>>>(pA, pY+2*SL, out+2*SL,
                               attn1_w+1024, attn1_b+16, attn2_w+1024, attn2_b+64, 16);
    k_gate<<<dim3(16,8),256>>>(pA, gate_b, out+2*SL, pB, 1, -1, -1, (float*)0);
    k_attn<<<dim3(16,8),128>>>(pB, pY+1*SL, out+1*SL,
                               attn1_w, attn1_b, attn2_w, attn2_b, 8);
    k_gate<<<dim3(16,8),256>>>(pB, gate_b, out+1*SL, out, 0, -1, -1, (float*)0);
}

// round 14
// speedup vs baseline: 1.1330x; 1.1330x over previous
#include <cuda_runtime.h>
#include <math.h>

#define Bn 8
#define Cn 64
#define Ln 2048
#define SL (Bn*Cn*Ln)
#define NT (4*SL)
#define TLX 128
#define SW 148
#define BW 146

typedef unsigned long long ull;

__device__ float g_coef[NT];
__device__ float g_y[NT];
__device__ float g_y2[NT];
__device__ float g_bufA[SL];
__device__ float g_bufB[SL];

__device__ float    g_stat[Bn*Cn];
__device__ float    g_lo[Bn*7];
__device__ float    g_hi[Bn*7];
__device__ float    g_sumP[16];
__device__ unsigned g_mnB[4];
__device__ unsigned g_mxB[4];
__device__ unsigned g_maxS[4];
__device__ float    g_ts[20];
__device__ float    g_dt[16];
__device__ float    g_G[64*128];
__device__ float2   g_w1D[4*192*64];
__device__ float2   g_w2D[4*192*64];
__device__ float    g_wgT[3*192*64];
__device__ float    g_w1d[4096];     /* dywan w1  transposed [c][o]   */
__device__ float    g_wg1d[8192];    /* dywan wg1 transposed [i][o]   */
__device__ float    g_wg2d[1792];    /* dywan wg2 transposed [i][j]   */
__device__ float    g_wmd[8192];     /* ode_wm transposed [lvl,d][o]  */
__device__ float    g_ein[32];
__device__ float    g_eout[32];
__device__ float    g_scale[32];
__device__ float    g_dummy[4];

__device__ __forceinline__ float geluf(float x){ return 0.5f*x*(1.0f+erff(x*0.70710678118654752f)); }
__device__ __forceinline__ float siluf(float x){ return x/(1.0f+expf(-x)); }
__device__ __forceinline__ float sigmf(float x){ return 1.0f/(1.0f+expf(-x)); }

__device__ __forceinline__ ull pk2(float lo, float hi){
    ull r; asm("mov.b64 %0, {%1, %2};" : "=l"(r) : "f"(lo), "f"(hi)); return r;
}
__device__ __forceinline__ void upk2(float& lo, float& hi, ull v){
    asm("mov.b64 {%0, %1}, %2;" : "=f"(lo), "=f"(hi) : "l"(v));
}
__device__ __forceinline__ ull fma2(ull a, ull b, ull c){
    ull d; asm("fma.rn.f32x2 %0, %1, %2, %3;" : "=l"(d) : "l"(a), "l"(b), "l"(c)); return d;
}

__global__ void k_reset(){
    int t=threadIdx.x;
    if(t<16){ g_sumP[t]=0.f; g_dt[t]=0.f; }
    if(t<4){ g_mnB[t]=0x7F800000u; g_mxB[t]=0u; g_maxS[t]=0u; }
    if(t<32){ g_ein[t]=0.f; g_eout[t]=0.f; }
}

__global__ void k_stat(const float* __restrict__ in){
    __shared__ float red[256];
    int row=blockIdx.x; const float* p=in+(size_t)row*Ln;
    float s=0.f;
    for(int i=threadIdx.x;i<Ln;i+=256) s+=p[i];
    red[threadIdx.x]=s; __syncthreads();
    for(int k=128;k;k>>=1){ if(threadIdx.x<k) red[threadIdx.x]+=red[threadIdx.x+k]; __syncthreads(); }
    if(!threadIdx.x) g_stat[row]=red[0]*(1.0f/Ln);
}

/* dywan MLP with transposed (coalesced) weights + parallel ortho */
__global__ void k_dywan(const float* __restrict__ b1,
                        const float* __restrict__ bg1,
                        const float* __restrict__ bg2,
                        float* __restrict__ orthoOut){
    __shared__ float sh1[512];
    __shared__ float sh2[1024];
    __shared__ float shf[112];
    __shared__ float shinv[8];
    __shared__ float red[256];
    __shared__ float sst[512];
    int t=threadIdx.x;
    for(int e=t;e<512;e+=256) sst[e]=g_stat[e];
    __syncthreads();
    for(int e=t;e<512;e+=256){
        int b=e>>6,o=e&63; float s=b1[o];
        const float* st=&sst[b*64];
        #pragma unroll 8
        for(int c=0;c<64;c++) s=fmaf(st[c],g_w1d[c*64+o],s);
        sh1[e]=geluf(s);
    }
    __syncthreads();
    for(int e=t;e<1024;e+=256){
        int b=e>>7,o=e&127; float s=bg1[o];
        #pragma unroll 8
        for(int i=0;i<64;i++) s=fmaf(sh1[b*64+i],g_wg1d[i*128+o],s);
        sh2[e]=geluf(s);
    }
    __syncthreads();
    if(t<112){
        int b=t/14, jj=t-b*14; float s=bg2[jj];
        #pragma unroll 8
        for(int i=0;i<128;i++) s=fmaf(sh2[b*128+i],g_wg2d[i*14+jj],s);
        shf[t]=s;
        if(jj<7) g_lo[b*7+jj]=s; else g_hi[b*7+(jj-7)]=s;
    }
    __syncthreads();
    float contrib=0.f;
    if(t<8){
        float n2=0.f;
        #pragma unroll
        for(int i=0;i<7;i++){ float v=shf[t*14+i]; n2=fmaf(v,v,n2); }
        float inv=1.f/(sqrtf(n2)+1e-8f);
        shinv[t]=inv;
        contrib += fabsf(n2*inv*inv-1.f)*(0.01f*0.125f);
    }
    __syncthreads();
    if(t<64){
        int b=t>>3, j2=t&7;
        float cur=(j2<7)?shf[b*14+j2]:0.f;
        float prev=(j2>0)?shf[b*14+j2-1]:0.f;
        contrib += fabsf(cur-prev)*(0.1f/64.f);
    }
    for(int idx=t; idx<1176; idx+=256){
        int b=idx/147, r=idx-b*147;
        int s=r/49+1, ij=r-(s-1)*49;
        int i=ij/7, j=ij-7*i;
        float inv=shinv[b];
        float a=shf[b*14+i]*inv;
        float c=shf[b*14+((j-s+7)%7)]*inv;
        contrib += fabsf(a*c)*(0.01f/392.f);
    }
    for(int o=16;o;o>>=1) contrib+=__shfl_down_sync(0xffffffffu,contrib,o);
    if((t&31)==0) red[t>>5]=contrib;
    __syncthreads();
    if(t==0){
        float r=0.f;
        for(int i=0;i<8;i++) r+=red[i];
        orthoOut[0]=r;
    }
}

__global__ void k_wfilt(const float* __restrict__ in, float* __restrict__ outLo,
                        float* __restrict__ outHi, float* __restrict__ dupLo,
                        float* __restrict__ dupHi, int doStat){
    __shared__ float xr[Ln+6];
    __shared__ float red[256];
    int row=blockIdx.x, b=row>>6;
    const float* p=in+(size_t)row*Ln;
    for(int j=threadIdx.x;j<Ln+6;j+=256){
        int gg=j-3; gg=min(max(gg,0),Ln-1);
        xr[j]=p[gg];
    }
    float fl[7],fh[7];
    #pragma unroll
    for(int k=0;k<7;k++){ fl[k]=g_lo[b*7+k]; fh[k]=g_hi[b*7+k]; }
    __syncthreads();
    float s=0.f;
    for(int l=threadIdx.x;l<Ln;l+=256){
        float aL=0.f,aH=0.f;
        #pragma unroll
        for(int k=0;k<7;k++){ float v=xr[l+k]; aL=fmaf(v,fl[k],aL); aH=fmaf(v,fh[k],aH); }
        size_t g=(size_t)row*Ln+l;
        outLo[g]=aL;
        outHi[g]=aH;
        if(dupLo) dupLo[g]=aL;
        if(dupHi) dupHi[g]=aH;
        s+=aL;
    }
    if(doStat){
        red[threadIdx.x]=s; __syncthreads();
        for(int k=128;k;k>>=1){ if(threadIdx.x<k) red[threadIdx.x]+=red[threadIdx.x+k]; __syncthreads(); }
        if(!threadIdx.x) g_stat[row]=red[0]*(1.0f/Ln);
    }
}

__device__ __forceinline__ float brSum(float v, float* sh){
    for(int o=16;o;o>>=1) v+=__shfl_down_sync(0xffffffffu,v,o);
    if((threadIdx.x&31)==0) sh[threadIdx.x>>5]=v;
    __syncthreads();
    float r=0.f;
    if(threadIdx.x==0){ for(int i=0;i<8;i++) r+=sh[i]; }
    __syncthreads();
    return r;
}
__device__ __forceinline__ float brMin(float v, float* sh){
    for(int o=16;o;o>>=1) v=fminf(v,__shfl_down_sync(0xffffffffu,v,o));
    if((threadIdx.x&31)==0) sh[threadIdx.x>>5]=v;
    __syncthreads();
    float r=3.4e38f;
    if(threadIdx.x==0){ for(int i=0;i<8;i++) r=fminf(r,sh[i]); }
    __syncthreads();
    return r;
}
__device__ __forceinline__ float brMax(float v, float* sh){
    for(int o=16;o;o>>=1) v=fmaxf(v,__shfl_down_sync(0xffffffffu,v,o));
    if((threadIdx.x&31)==0) sh[threadIdx.x>>5]=v;
    __syncthreads();
    float r=0.f;
    if(threadIdx.x==0){ for(int i=0;i<8;i++) r=fmaxf(r,sh[i]); }
    __syncthreads();
    return r;
}

__global__ void k_tgrid(){
    __shared__ float xr[Ln];
    __shared__ float ga[Ln];
    __shared__ float sh[8];
    int row=blockIdx.x, lvl=blockIdx.y, t=threadIdx.x;
    const float* p=g_coef + (size_t)lvl*SL + (size_t)row*Ln;
    float e=0.f;
    for(int i=t;i<Ln;i+=256){ float v=p[i]; xr[i]=v; e=fmaf(v,v,e); }
    __syncthreads();
    for(int i=t;i<Ln-1;i+=256) ga[i]=fabsf(xr[i+1]-xr[i]);
    __syncthreads();
    float s0=0.f,s1=0.f,s2=0.f,s3=0.f,mn=3.4e38f,mx=0.f;
    for(int i=t;i<2047;i+=256){
        int a=i-2; if(a<0)a=0;
        int b=i+2; if(b>2046)b=2046;
        float v=0.f;
        for(int m=a;m<=b;m++) v+=ga[m];
        v*=0.2f;
        mn=fminf(mn,v); mx=fmaxf(mx,v);
        if(i<511)  s0+=v;
        if(i<1023) s1+=v;
        if(i<1534) s2+=v;
        if(i<2046) s3+=v;
    }
    float re=brSum(e,sh);
    float r0=brSum(s0,sh), r1=brSum(s1,sh), r2=brSum(s2,sh), r3=brSum(s3,sh);
    float rmn=brMin(mn,sh), rmx=brMax(mx,sh);
    if(t==0){
        atomicAdd(&g_ein[lvl*8+(row>>6)],re);
        atomicAdd(&g_sumP[lvl*4+0],r0);
        atomicAdd(&g_sumP[lvl*4+1],r1);
        atomicAdd(&g_sumP[lvl*4+2],r2);
        atomicAdd(&g_sumP[lvl*4+3],r3);
        atomicMin(&g_mnB[lvl],__float_as_uint(rmn));
        atomicMax(&g_mxB[lvl],__float_as_uint(rmx));
        atomicMax(&g_maxS[lvl],__float_as_uint(r3));
    }
}

__global__ void k_ts(){
    int lvl=threadIdx.x;
    if(lvl>=4) return;
    float mn=__uint_as_float(g_mnB[lvl]);
    float mx=__uint_as_float(g_mxB[lvl]);
    const int IDX[5]={0,511,1023,1534,2046};
    float ts[5]; ts[0]=0.f;
    float tgmax;
    if(mx-mn<1e-8f){
        for(int k=1;k<5;k++) ts[k]=0.5f*(float)IDX[k];
        tgmax=0.5f*2046.f;
    }else{
        float sc=0.9f/(mx-mn+1e-30f);
        for(int k=1;k<5;k++){
            float meanS=g_sumP[lvl*4+(k-1)]*(1.f/512.f);
            ts[k]=(float)IDX[k]*0.1f + sc*(meanS-(float)IDX[k]*mn);
        }
        float maxS=__uint_as_float(g_maxS[lvl]);
        tgmax=2046.f*0.1f + sc*(maxS-2046.f*mn);
    }
    tgmax=fmaxf(tgmax,1e-12f);
    float inv=1.f/tgmax;
    for(int k=0;k<5;k++){ ts[k]*=inv; g_ts[lvl*5+k]=ts[k]; }
    for(int j=0;j<4;j++) g_dt[lvl*4+j]=ts[j+1]-ts[j];
}

__global__ void k_modtab(const float* __restrict__ wt,const float* __restrict__ bt,
                         const float* __restrict__ bm,
                         const float* __restrict__ emb){
    for(int idx=threadIdx.x; idx<64*128; idx+=256){
        int combo=idx>>7, o=idx&127;
        int lvl=combo>>4, j=(combo>>2)&3, ev=combo&3;
        float t0=g_ts[lvl*5+j], t1=g_ts[lvl*5+j+1];
        float tt=(ev==0)?t0:((ev==3)?t1:(t0+0.5f*(t1-t0)));
        float s=bm[lvl*128+o];
        #pragma unroll
        for(int d=0;d<16;d++){
            float te=wt[lvl*16+d]*tt+bt[lvl*16+d];
            te=siluf(te);
            s=fmaf(g_wmd[(lvl*16+d)*128+o],te,s);
        }
        if(o<64) g_G[combo*128+o]=1.f+s+emb[(lvl*8+lvl)*64+o];
        else     g_G[combo*128+o]=s;
    }
}

__global__ void k_wprep(const float* __restrict__ c1,const float* __restrict__ c2,
                        const float* __restrict__ gw,
                        const float* __restrict__ dw1,const float* __restrict__ dwg1,
                        const float* __restrict__ dwg2,const float* __restrict__ wm){
    int i=blockIdx.x*256+threadIdx.x;
    if(i<4*12288){
        int lvl=i/12288, r=i-lvl*12288, ck=r>>6, o=r&63, c=ck/3, k=ck-3*c;
        int src=lvl*12288+o*192+c*3+k;
        float v1=c1[src], v2=c2[src];
        g_w1D[i]=make_float2(v1,v1);
        g_w2D[i]=make_float2(v2,v2);
        if(lvl<3) g_wgT[i]=gw[src];
    }
    if(i<4096)  g_w1d[i] =dw1[(i&63)*64+(i>>6)];
    if(i<8192)  g_wg1d[i]=dwg1[(i&127)*64+(i>>7)];
    if(i<1792)  g_wg2d[i]=dwg2[(i%14)*128+(i/14)];
    if(i<8192){
        int lvl=i>>11, d=(i>>7)&15, o=i&127;
        g_wmd[i]=wm[(lvl*128+o)*16+d];
    }
}

/* conv stage inside fused RK (FFMA2 packed, R9 layout) */
template<int ACT>
__device__ __forceinline__ void conv_stage(const float* src, float* dst,
    const float2* wD, const float* bias, const float* ga, const float* be,
    int cb, int lane, int l0)
{
    ull A0[9],A1[9];
    #pragma unroll
    for(int p=0;p<9;p++){A0[p]=0ull;A1[p]=0ull;}

    for(int c=0;c<64;c++){
        const float2* row=(const float2*)(src + c*SW + (cb-1));
        float2 F[10];
        #pragma unroll
        for(int i=0;i<10;i++) F[i]=row[i];
        const float2* wp=wD + c*192;
        float2 f00=wp[lane],    f01=wp[64+lane],  f02=wp[128+lane];
        float2 f10=wp[32+lane], f11=wp[96+lane],  f12=wp[160+lane];
        ull w00=pk2(f00.x,f00.y), w01=pk2(f01.x,f01.y), w02=pk2(f02.x,f02.y);
        ull w10=pk2(f10.x,f10.y), w11=pk2(f11.x,f11.y), w12=pk2(f12.x,f12.y);
        #pragma unroll
        for(int p=0;p<9;p++){
            ull e0=pk2(F[p].x,  F[p].y);
            ull od=pk2(F[p].y,  F[p+1].x);
            ull e1=pk2(F[p+1].x,F[p+1].y);
            A0[p]=fma2(e0,w00,A0[p]);
            A0[p]=fma2(od,w01,A0[p]);
            A0[p]=fma2(e1,w02,A0[p]);
            A1[p]=fma2(e0,w10,A1[p]);
            A1[p]=fma2(od,w11,A1[p]);
            A1[p]=fma2(e1,w12,A1[p]);
        }
    }

    float b0=bias[lane], b1=bias[lane+32];
    float g0=0.f,g1=0.f,bb0=0.f,bb1=0.f;
    if(ACT==1){ g0=ga[lane]; g1=ga[lane+32]; bb0=be[lane]; bb1=be[lane+32]; }

    #pragma unroll
    for(int p=0;p<9;p++){
        float v0,v1,u0,u1;
        upk2(v0,v1,A0[p]);
        upk2(u0,u1,A1[p]);
        int col=cb+2*p;
        #pragma unroll
        for(int q=0;q<2;q++){
            float vA=(q==0)?v0:v1, vB=(q==0)?u0:u1;
            int cc=col+q;
            int g=l0-9+cc;
            bool inr=(g>=0)&&(g<Ln);
            int a0=lane*SW+cc, a1=(lane+32)*SW+cc;
            if(ACT==0){
                dst[a0]=inr?geluf(vA+b0):0.f;
                dst[a1]=inr?geluf(vB+b1):0.f;
            }else{
                float y0=dst[a0], y1=dst[a1];
                float m0=fmaf(vA+b0,g0,bb0);
                float m1=fmaf(vB+b1,g1,bb1);
                dst[a0]=inr?(siluf(m0)-0.1f*y0):0.f;
                dst[a1]=inr?(siluf(m1)-0.1f*y1):0.f;
            }
        }
    }
}

/* fused RK4 step (R9 best config: 256 threads, acc in regs); j==3 adds e_out */
__global__ void __launch_bounds__(256,2) k_rk(
    const float* __restrict__ yIn, float* __restrict__ yOut,
    const float* __restrict__ b1All, const float* __restrict__ b2All, int j)
{
    extern __shared__ float smx[];
    float* A  = smx;
    float* Bf = smx + 64*SW;
    __shared__ float redE[8];
    int t=threadIdx.x, lane=t&31, w=t>>5;
    int slab=blockIdx.y, lvl=slab>>3;
    size_t soff=(size_t)slab*(Cn*Ln);
    int l0=blockIdx.x*TLX;
    int cb=1+18*w;

    float dt=g_dt[lvl*4+j];
    const float2* w1D=g_w1D+lvl*12288;
    const float2* w2D=g_w2D+lvl*12288;
    const float* bias1=b1All+lvl*64;
    const float* bias2=b2All+lvl*64;
    const float* yS=yIn+soff;

    float acc[32];
    #pragma unroll
    for(int i=0;i<32;i++) acc[i]=0.f;

    for(int idx=t; idx<64*BW; idx+=256){
        int c=idx/BW, b=idx-c*BW;
        int g=l0-9+b;
        A[c*SW+b]=(g>=0&&g<Ln)? yS[(size_t)c*Ln+g] : 0.f;
    }
    for(int idx=t; idx<128; idx+=256){
        int c=idx>>1, col=(idx&1)?(BW-1):0;
        Bf[c*SW+col]=0.f;
    }
    __syncthreads();

    for(int ev=0; ev<4; ev++){
        float* inB=(ev&1)?Bf:A;
        float* hB =(ev&1)?A:Bf;
        float kcoef=(ev==1||ev==2)?2.f:1.f;

        conv_stage<0>(inB,hB,w1D,bias1,(const float*)0,(const float*)0,cb,lane,l0);
        __syncthreads();
        const float* Gp=g_G+((lvl*4+j)*4+ev)*128;
        conv_stage<1>(hB,inB,w2D,bias2,Gp,Gp+64,cb,lane,l0);
        __syncthreads();

        float* kB=inB;
        #pragma unroll
        for(int i=0;i<32;i++){
            int idx=t+i*256;
            int c=idx>>7, l=idx&127;
            acc[i]=fmaf(kcoef,kB[c*SW+l+9],acc[i]);
        }
        if(ev<3){
            float aN=(ev==2)?dt:0.5f*dt;
            for(int idx=t; idx<64*BW; idx+=256){
                int c=idx/BW, b=idx-c*BW;
                int g=l0-9+b;
                float v=0.f;
                if(g>=0&&g<Ln) v=fmaf(aN,kB[c*SW+b],yS[(size_t)c*Ln+g]);
                hB[c*SW+b]=v;
            }
        }
        __syncthreads();
    }

    float s6=dt*(1.f/6.f);
    float esum=0.f;
    #pragma unroll
    for(int i=0;i<32;i++){
        int idx=t+i*256;
        int c=idx>>7, l=idx&127;
        size_t g=soff+(size_t)c*Ln+l0+l;
        float yv=fmaf(s6,acc[i],yIn[g]);
        yOut[g]=yv;
        esum=fmaf(yv,yv,esum);
    }
    if(j==3){
        for(int o=16;o;o>>=1) esum+=__shfl_down_sync(0xffffffffu,esum,o);
        if(lane==0) redE[w]=esum;
        __syncthreads();
        if(t==0){
            float r=0.f;
            for(int i=0;i<8;i++) r+=redE[i];
            atomicAdd(&g_eout[slab],r);
        }
    }
}

__global__ void k_sc(){
    int i=threadIdx.x;
    if(i<32){
        float einm =g_ein[i]*(1.f/(float)(Cn*Ln));
        float eoutm=g_eout[i]*(1.f/(float)(Cn*Ln));
        g_scale[i]=sqrtf(einm/(eoutm+1e-8f));
    }
}

__global__ void __launch_bounds__(256) k_gate(
    const float* __restrict__ cur, const float* __restrict__ bAll,
    const float* __restrict__ det, float* __restrict__ outp, int gi,
    int curBase, int detBase, float* __restrict__ detCopy)
{
    __shared__ float xs[64*130];
    int t=threadIdx.x;
    int slab=blockIdx.y;
    size_t soff=(size_t)slab*(Cn*Ln);
    int l0=blockIdx.x*TLX;
    const float* wT=g_wgT+gi*12288;
    const float* ip=cur+soff;
    float sc=(curBase>=0)?g_scale[curBase+slab]:1.f;
    float sd=(detBase>=0)?g_scale[detBase+slab]:1.f;

    for(int idx=t; idx<64*130; idx+=256){
        int c=idx/130, jj=idx-130*c;
        int gl=l0-1+jj;
        xs[idx]=(gl>=0&&gl<Ln)? ip[(size_t)c*Ln+gl]*sc : 0.f;
    }
    __syncthreads();

    int lane=t&31, w=t>>5;
    int base=w*16;
    float acc0[16],acc1[16];
    #pragma unroll
    for(int i=0;i<16;i++){acc0[i]=0.f;acc1[i]=0.f;}

    for(int c=0;c<64;c++){
        float xv[18];
        #pragma unroll
        for(int i2=0;i2<18;i2++) xv[i2]=xs[c*130+base+i2];
        const float* wp=wT+c*192;
        float w00=__ldg(wp+lane),     w01=__ldg(wp+64+lane),  w02=__ldg(wp+128+lane);
        float w10=__ldg(wp+32+lane),  w11=__ldg(wp+96+lane),  w12=__ldg(wp+160+lane);
        #pragma unroll
        for(int i2=0;i2<16;i2++){
            acc0[i2]=fmaf(xv[i2],w00,fmaf(xv[i2+1],w01,fmaf(xv[i2+2],w02,acc0[i2])));
            acc1[i2]=fmaf(xv[i2],w10,fmaf(xv[i2+1],w11,fmaf(xv[i2+2],w12,acc1[i2])));
        }
    }
    __syncthreads();
    #pragma unroll
    for(int i2=0;i2<16;i2++){
        xs[lane*130+base+i2]=acc0[i2];
        xs[(lane+32)*130+base+i2]=acc1[i2];
    }
    __syncthreads();

    const float* bptr=bAll+gi*64;
    for(int idx=t; idx<64*TLX; idx+=256){
        int c=idx>>7, l=idx&127;
        float v=xs[c*130+l]+bptr[c];
        size_t g=soff+(size_t)c*Ln+l0+l;
        float gt=sigmf(v);
        float dv=det[g]*sd;
        outp[g]=fmaf(gt,dv,cur[g]*sc);
        if(detCopy) detCopy[g]=dv;
    }
}

__global__ void k_attn(const float* __restrict__ cur, const float* __restrict__ det,
                       float* __restrict__ out, const float* __restrict__ w1,
                       const float* __restrict__ b1, const float* __restrict__ w2,
                       const float* __restrict__ b2, int detBase){
    int b=blockIdx.y;
    int l=blockIdx.x*128+threadIdx.x;
    size_t base=(size_t)b*(Cn*Ln)+l;
    float sd=g_scale[detBase+b];
    float h[16];
    #pragma unroll
    for(int i=0;i<16;i++) h[i]=b1[i];
    for(int c=0;c<64;c++){
        float v=cur[base+(size_t)c*Ln];
        #pragma unroll
        for(int i=0;i<16;i++) h[i]=fmaf(v,__ldg(w1+i*64+c),h[i]);
    }
    #pragma unroll
    for(int i=0;i<16;i++) h[i]=geluf(h[i]);
    for(int o=0;o<64;o++){
        float s=b2[o];
        #pragma unroll
        for(int i=0;i<16;i++) s=fmaf(h[i],__ldg(w2+o*16+i),s);
        float a=sigmf(s);
        size_t g=base+(size_t)o*Ln;
        out[g]=det[g]*sd*(1.f+a);
    }
}

extern "C" void kernel_launch(void* const* d_in, const int* in_sizes, int n_in,
                              void* d_out, int out_size){
    const float* x       =(const float*)d_in[0];
    const float* dy_w1   =(const float*)d_in[1];
    const float* dy_b1   =(const float*)d_in[2];
    const float* dy_wg1  =(const float*)d_in[3];
    const float* dy_bg1  =(const float*)d_in[4];
    const float* dy_wg2  =(const float*)d_in[5];
    const float* dy_bg2  =(const float*)d_in[6];
    const float* ode_c1w =(const float*)d_in[7];
    const float* ode_c1b =(const float*)d_in[8];
    const float* ode_c2w =(const float*)d_in[9];
    const float* ode_c2b =(const float*)d_in[10];
    const float* ode_wt  =(const float*)d_in[11];
    const float* ode_bt  =(const float*)d_in[12];
    const float* ode_wm  =(const float*)d_in[13];
    const float* ode_bm  =(const float*)d_in[14];
    const float* ode_emb =(const float*)d_in[15];
    const float* gate_w  =(const float*)d_in[16];
    const float* gate_b  =(const float*)d_in[17];
    const float* attn1_w =(const float*)d_in[18];
    const float* attn1_b =(const float*)d_in[19];
    const float* attn2_w =(const float*)d_in[20];
    const float* attn2_b =(const float*)d_in[21];
    float* out=(float*)d_out;

    void *vp;
    cudaGetSymbolAddress(&vp,g_coef);  float* pCoef=(float*)vp;
    cudaGetSymbolAddress(&vp,g_y);     float* pY   =(float*)vp;
    cudaGetSymbolAddress(&vp,g_y2);    float* pY2  =(float*)vp;
    cudaGetSymbolAddress(&vp,g_bufA);  float* pA   =(float*)vp;
    cudaGetSymbolAddress(&vp,g_bufB);  float* pB   =(float*)vp;
    cudaGetSymbolAddress(&vp,g_dummy); float* pDum =(float*)vp;

    float* orthoPtr=(out_size>NT)?(out+NT):pDum;

    const int shz = 2*64*SW*(int)sizeof(float);   /* 75776 B */
    cudaFuncSetAttribute(k_rk, cudaFuncAttributeMaxDynamicSharedMemorySize, shz);

    k_reset<<<1,32>>>();
    k_wprep<<<192,256>>>(ode_c1w,ode_c2w,gate_w,dy_w1,dy_wg1,dy_wg2,ode_wm);
    k_stat<<<512,256>>>(x);
    k_dywan<<<1,256>>>(dy_b1,dy_bg1,dy_bg2,orthoPtr);
    k_wfilt<<<512,256>>>(x,  pA, pCoef+1*SL, (float*)0, pY+1*SL, 1);
    k_dywan<<<1,256>>>(dy_b1,dy_bg1,dy_bg2,orthoPtr);
    k_wfilt<<<512,256>>>(pA, pB, pCoef+2*SL, (float*)0, pY+2*SL, 1);
    k_dywan<<<1,256>>>(dy_b1,dy_bg1,dy_bg2,orthoPtr);
    k_wfilt<<<512,256>>>(pB, pCoef, pCoef+3*SL, pY, pY+3*SL, 0);

    k_tgrid<<<dim3(512,4),256>>>();
    k_ts<<<1,32>>>();
    k_modtab<<<1,256>>>(ode_wt,ode_bt,ode_bm,ode_emb);

    /* fused RK4: y ping-pongs y <-> y2, ends in y; j=3 accumulates e_out */
    k_rk<<<dim3(16,32),256,shz>>>(pY,  pY2, ode_c1b, ode_c2b, 0);
    k_rk<<<dim3(16,32),256,shz>>>(pY2, pY,  ode_c1b, ode_c2b, 1);
    k_rk<<<dim3(16,32),256,shz>>>(pY,  pY2, ode_c1b, ode_c2b, 2);
    k_rk<<<dim3(16,32),256,shz>>>(pY2, pY,  ode_c1b, ode_c2b, 3);

    k_sc<<<1,32>>>();

    k_gate<<<dim3(16,8),256>>>(pY, gate_b, pY+3*SL, pA, 2, 0, 24, out+3*SL);
    k_attn<<<dim3(16,8),128>>>(pA, pY+2*SL, out+2*SL,
                               attn1_w+1024, attn1_b+16, attn2_w+1024, attn2_b+64, 16);
    k_gate<<<dim3(16,8),256>>>(pA, gate_b, out+2*SL, pB, 1, -1, -1, (float*)0);
    k_attn<<<dim3(16,8),128>>>(pB, pY+1*SL, out+1*SL,
                               attn1_w, attn1_b, attn2_w, attn2_b, 8);
    k_gate<<<dim3(16,8),256>>>(pB, gate_b, out+1*SL, out, 0, -1, -1, (float*)0);
}

// round 16
// speedup vs baseline: 1.1658x; 1.0290x over previous
#include <cuda_runtime.h>
#include <math.h>

#define Bn 8
#define Cn 64
#define Ln 2048
#define SL (Bn*Cn*Ln)
#define NT (4*SL)
#define TLX 128
#define SW 148
#define BW 146

typedef unsigned long long ull;

__device__ float g_coef[NT];
__device__ float g_y[NT];
__device__ float g_y2[NT];
__device__ float g_bufA[SL];
__device__ float g_bufB[SL];

__device__ float    g_stat[Bn*Cn];
__device__ float    g_lo[Bn*7];
__device__ float    g_hi[Bn*7];
__device__ float    g_sumP[16];
__device__ unsigned g_mnB[4];
__device__ unsigned g_mxB[4];
__device__ unsigned g_maxS[4];
__device__ float    g_ts[20];
__device__ float    g_dt[16];
__device__ float    g_G[64*128];
__device__ float    g_w1T[4*192*64];
__device__ float    g_w2T[4*192*64];
__device__ float    g_wgT[3*192*64];
__device__ float    g_w1d[4096];     /* dywan w1  transposed [c][o]   */
__device__ float    g_wg1d[8192];    /* dywan wg1 transposed [i][o]   */
__device__ float    g_wg2d[1792];    /* dywan wg2 transposed [i][j]   */
__device__ float    g_wmd[8192];     /* ode_wm transposed [lvl,d][o]  */
__device__ float    g_ein[32];
__device__ float    g_eout[32];
__device__ float    g_scale[32];
__device__ float    g_dummy[4];

__device__ __forceinline__ float geluf(float x){ return 0.5f*x*(1.0f+erff(x*0.70710678118654752f)); }
__device__ __forceinline__ float siluf(float x){ return x/(1.0f+expf(-x)); }
__device__ __forceinline__ float sigmf(float x){ return 1.0f/(1.0f+expf(-x)); }

__device__ __forceinline__ ull pk2(float lo, float hi){
    ull r; asm("mov.b64 %0, {%1, %2};" : "=l"(r) : "f"(lo), "f"(hi)); return r;
}
__device__ __forceinline__ void upk2(float& lo, float& hi, ull v){
    asm("mov.b64 {%0, %1}, %2;" : "=f"(lo), "=f"(hi) : "l"(v));
}
__device__ __forceinline__ ull fma2(ull a, ull b, ull c){
    ull d; asm("fma.rn.f32x2 %0, %1, %2, %3;" : "=l"(d) : "l"(a), "l"(b), "l"(c)); return d;
}

__global__ void k_reset(){
    int t=threadIdx.x;
    if(t<16){ g_sumP[t]=0.f; g_dt[t]=0.f; }
    if(t<4){ g_mnB[t]=0x7F800000u; g_mxB[t]=0u; g_maxS[t]=0u; }
    if(t<32){ g_ein[t]=0.f; g_eout[t]=0.f; }
}

__global__ void k_stat(const float* __restrict__ in){
    __shared__ float red[256];
    int row=blockIdx.x; const float* p=in+(size_t)row*Ln;
    float s=0.f;
    for(int i=threadIdx.x;i<Ln;i+=256) s+=p[i];
    red[threadIdx.x]=s; __syncthreads();
    for(int k=128;k;k>>=1){ if(threadIdx.x<k) red[threadIdx.x]+=red[threadIdx.x+k]; __syncthreads(); }
    if(!threadIdx.x) g_stat[row]=red[0]*(1.0f/Ln);
}

/* dywan MLP with transposed (coalesced) weights + parallel ortho */
__global__ void k_dywan(const float* __restrict__ b1,
                        const float* __restrict__ bg1,
                        const float* __restrict__ bg2,
                        float* __restrict__ orthoOut){
    __shared__ float sh1[512];
    __shared__ float sh2[1024];
    __shared__ float shf[112];
    __shared__ float shinv[8];
    __shared__ float red[256];
    __shared__ float sst[512];
    int t=threadIdx.x;
    for(int e=t;e<512;e+=256) sst[e]=g_stat[e];
    __syncthreads();
    for(int e=t;e<512;e+=256){
        int b=e>>6,o=e&63; float s=b1[o];
        const float* st=&sst[b*64];
        #pragma unroll 8
        for(int c=0;c<64;c++) s=fmaf(st[c],g_w1d[c*64+o],s);
        sh1[e]=geluf(s);
    }
    __syncthreads();
    for(int e=t;e<1024;e+=256){
        int b=e>>7,o=e&127; float s=bg1[o];
        #pragma unroll 8
        for(int i=0;i<64;i++) s=fmaf(sh1[b*64+i],g_wg1d[i*128+o],s);
        sh2[e]=geluf(s);
    }
    __syncthreads();
    if(t<112){
        int b=t/14, jj=t-b*14; float s=bg2[jj];
        #pragma unroll 8
        for(int i=0;i<128;i++) s=fmaf(sh2[b*128+i],g_wg2d[i*14+jj],s);
        shf[t]=s;
        if(jj<7) g_lo[b*7+jj]=s; else g_hi[b*7+(jj-7)]=s;
    }
    __syncthreads();
    float contrib=0.f;
    if(t<8){
        float n2=0.f;
        #pragma unroll
        for(int i=0;i<7;i++){ float v=shf[t*14+i]; n2=fmaf(v,v,n2); }
        float inv=1.f/(sqrtf(n2)+1e-8f);
        shinv[t]=inv;
        contrib += fabsf(n2*inv*inv-1.f)*(0.01f*0.125f);
    }
    __syncthreads();
    if(t<64){
        int b=t>>3, j2=t&7;
        float cur=(j2<7)?shf[b*14+j2]:0.f;
        float prev=(j2>0)?shf[b*14+j2-1]:0.f;
        contrib += fabsf(cur-prev)*(0.1f/64.f);
    }
    for(int idx=t; idx<1176; idx+=256){
        int b=idx/147, r=idx-b*147;
        int s=r/49+1, ij=r-(s-1)*49;
        int i=ij/7, j=ij-7*i;
        float inv=shinv[b];
        float a=shf[b*14+i]*inv;
        float c=shf[b*14+((j-s+7)%7)]*inv;
        contrib += fabsf(a*c)*(0.01f/392.f);
    }
    for(int o=16;o;o>>=1) contrib+=__shfl_down_sync(0xffffffffu,contrib,o);
    if((t&31)==0) red[t>>5]=contrib;
    __syncthreads();
    if(t==0){
        float r=0.f;
        for(int i=0;i<8;i++) r+=red[i];
        orthoOut[0]=r;
    }
}

__global__ void k_wfilt(const float* __restrict__ in, float* __restrict__ outLo,
                        float* __restrict__ outHi, float* __restrict__ dupLo,
                        float* __restrict__ dupHi, int doStat){
    __shared__ float xr[Ln+6];
    __shared__ float red[256];
    int row=blockIdx.x, b=row>>6;
    const float* p=in+(size_t)row*Ln;
    for(int j=threadIdx.x;j<Ln+6;j+=256){
        int gg=j-3; gg=min(max(gg,0),Ln-1);
        xr[j]=p[gg];
    }
    float fl[7],fh[7];
    #pragma unroll
    for(int k=0;k<7;k++){ fl[k]=g_lo[b*7+k]; fh[k]=g_hi[b*7+k]; }
    __syncthreads();
    float s=0.f;
    for(int l=threadIdx.x;l<Ln;l+=256){
        float aL=0.f,aH=0.f;
        #pragma unroll
        for(int k=0;k<7;k++){ float v=xr[l+k]; aL=fmaf(v,fl[k],aL); aH=fmaf(v,fh[k],aH); }
        size_t g=(size_t)row*Ln+l;
        outLo[g]=aL;
        outHi[g]=aH;
        if(dupLo) dupLo[g]=aL;
        if(dupHi) dupHi[g]=aH;
        s+=aL;
    }
    if(doStat){
        red[threadIdx.x]=s; __syncthreads();
        for(int k=128;k;k>>=1){ if(threadIdx.x<k) red[threadIdx.x]+=red[threadIdx.x+k]; __syncthreads(); }
        if(!threadIdx.x) g_stat[row]=red[0]*(1.0f/Ln);
    }
}

__device__ __forceinline__ float brSum(float v, float* sh){
    for(int o=16;o;o>>=1) v+=__shfl_down_sync(0xffffffffu,v,o);
    if((threadIdx.x&31)==0) sh[threadIdx.x>>5]=v;
    __syncthreads();
    float r=0.f;
    if(threadIdx.x==0){ for(int i=0;i<8;i++) r+=sh[i]; }
    __syncthreads();
    return r;
}
__device__ __forceinline__ float brMin(float v, float* sh){
    for(int o=16;o;o>>=1) v=fminf(v,__shfl_down_sync(0xffffffffu,v,o));
    if((threadIdx.x&31)==0) sh[threadIdx.x>>5]=v;
    __syncthreads();
    float r=3.4e38f;
    if(threadIdx.x==0){ for(int i=0;i<8;i++) r=fminf(r,sh[i]); }
    __syncthreads();
    return r;
}
__device__ __forceinline__ float brMax(float v, float* sh){
    for(int o=16;o;o>>=1) v=fmaxf(v,__shfl_down_sync(0xffffffffu,v,o));
    if((threadIdx.x&31)==0) sh[threadIdx.x>>5]=v;
    __syncthreads();
    float r=0.f;
    if(threadIdx.x==0){ for(int i=0;i<8;i++) r=fmaxf(r,sh[i]); }
    __syncthreads();
    return r;
}

__global__ void k_tgrid(){
    __shared__ float xr[Ln];
    __shared__ float ga[Ln];
    __shared__ float sh[8];
    int row=blockIdx.x, lvl=blockIdx.y, t=threadIdx.x;
    const float* p=g_coef + (size_t)lvl*SL + (size_t)row*Ln;
    float e=0.f;
    for(int i=t;i<Ln;i+=256){ float v=p[i]; xr[i]=v; e=fmaf(v,v,e); }
    __syncthreads();
    for(int i=t;i<Ln-1;i+=256) ga[i]=fabsf(xr[i+1]-xr[i]);
    __syncthreads();
    float s0=0.f,s1=0.f,s2=0.f,s3=0.f,mn=3.4e38f,mx=0.f;
    for(int i=t;i<2047;i+=256){
        int a=i-2; if(a<0)a=0;
        int b=i+2; if(b>2046)b=2046;
        float v=0.f;
        for(int m=a;m<=b;m++) v+=ga[m];
        v*=0.2f;
        mn=fminf(mn,v); mx=fmaxf(mx,v);
        if(i<511)  s0+=v;
        if(i<1023) s1+=v;
        if(i<1534) s2+=v;
        if(i<2046) s3+=v;
    }
    float re=brSum(e,sh);
    float r0=brSum(s0,sh), r1=brSum(s1,sh), r2=brSum(s2,sh), r3=brSum(s3,sh);
    float rmn=brMin(mn,sh), rmx=brMax(mx,sh);
    if(t==0){
        atomicAdd(&g_ein[lvl*8+(row>>6)],re);
        atomicAdd(&g_sumP[lvl*4+0],r0);
        atomicAdd(&g_sumP[lvl*4+1],r1);
        atomicAdd(&g_sumP[lvl*4+2],r2);
        atomicAdd(&g_sumP[lvl*4+3],r3);
        atomicMin(&g_mnB[lvl],__float_as_uint(rmn));
        atomicMax(&g_mxB[lvl],__float_as_uint(rmx));
        atomicMax(&g_maxS[lvl],__float_as_uint(r3));
    }
}

__global__ void k_ts(){
    int lvl=threadIdx.x;
    if(lvl>=4) return;
    float mn=__uint_as_float(g_mnB[lvl]);
    float mx=__uint_as_float(g_mxB[lvl]);
    const int IDX[5]={0,511,1023,1534,2046};
    float ts[5]; ts[0]=0.f;
    float tgmax;
    if(mx-mn<1e-8f){
        for(int k=1;k<5;k++) ts[k]=0.5f*(float)IDX[k];
        tgmax=0.5f*2046.f;
    }else{
        float sc=0.9f/(mx-mn+1e-30f);
        for(int k=1;k<5;k++){
            float meanS=g_sumP[lvl*4+(k-1)]*(1.f/512.f);
            ts[k]=(float)IDX[k]*0.1f + sc*(meanS-(float)IDX[k]*mn);
        }
        float maxS=__uint_as_float(g_maxS[lvl]);
        tgmax=2046.f*0.1f + sc*(maxS-2046.f*mn);
    }
    tgmax=fmaxf(tgmax,1e-12f);
    float inv=1.f/tgmax;
    for(int k=0;k<5;k++){ ts[k]*=inv; g_ts[lvl*5+k]=ts[k]; }
    for(int j=0;j<4;j++) g_dt[lvl*4+j]=ts[j+1]-ts[j];
}

__global__ void k_modtab(const float* __restrict__ wt,const float* __restrict__ bt,
                         const float* __restrict__ bm,
                         const float* __restrict__ emb){
    for(int idx=threadIdx.x; idx<64*128; idx+=256){
        int combo=idx>>7, o=idx&127;
        int lvl=combo>>4, j=(combo>>2)&3, ev=combo&3;
        float t0=g_ts[lvl*5+j], t1=g_ts[lvl*5+j+1];
        float tt=(ev==0)?t0:((ev==3)?t1:(t0+0.5f*(t1-t0)));
        float s=bm[lvl*128+o];
        #pragma unroll
        for(int d=0;d<16;d++){
            float te=wt[lvl*16+d]*tt+bt[lvl*16+d];
            te=siluf(te);
            s=fmaf(g_wmd[(lvl*16+d)*128+o],te,s);
        }
        if(o<64) g_G[combo*128+o]=1.f+s+emb[(lvl*8+lvl)*64+o];
        else     g_G[combo*128+o]=s;
    }
}

__global__ void k_wprep(const float* __restrict__ c1,const float* __restrict__ c2,
                        const float* __restrict__ gw,
                        const float* __restrict__ dw1,const float* __restrict__ dwg1,
                        const float* __restrict__ dwg2,const float* __restrict__ wm){
    int i=blockIdx.x*256+threadIdx.x;
    if(i<4*12288){
        int lvl=i/12288, r=i-lvl*12288, ck=r>>6, o=r&63, c=ck/3, k=ck-3*c;
        int src=lvl*12288+o*192+c*3+k;
        g_w1T[i]=c1[src];
        g_w2T[i]=c2[src];
        if(lvl<3) g_wgT[i]=gw[src];
    }
    if(i<4096)  g_w1d[i] =dw1[(i&63)*64+(i>>6)];
    if(i<8192)  g_wg1d[i]=dwg1[(i&127)*64+(i>>7)];
    if(i<1792)  g_wg2d[i]=dwg2[(i%14)*128+(i/14)];
    if(i<8192){
        int lvl=i>>11, d=(i>>7)&15, o=i&127;
        g_wmd[i]=wm[(lvl*128+o)*16+d];
    }
}

/* conv stage inside fused RK (FFMA2 packed, scalar weight loads -> L1-resident) */
template<int ACT>
__device__ __forceinline__ void conv_stage(const float* src, float* dst,
    const float* wT, const float* bias, const float* ga, const float* be,
    int cb, int lane, int l0)
{
    ull A0[9],A1[9];
    #pragma unroll
    for(int p=0;p<9;p++){A0[p]=0ull;A1[p]=0ull;}

    for(int c=0;c<64;c++){
        const float2* row=(const float2*)(src + c*SW + (cb-1));
        float2 F[10];
        #pragma unroll
        for(int i=0;i<10;i++) F[i]=row[i];
        const float* wp=wT+c*192;
        float s00=__ldg(wp+lane),     s01=__ldg(wp+64+lane),  s02=__ldg(wp+128+lane);
        float s10=__ldg(wp+32+lane),  s11=__ldg(wp+96+lane),  s12=__ldg(wp+160+lane);
        ull w00=pk2(s00,s00), w01=pk2(s01,s01), w02=pk2(s02,s02);
        ull w10=pk2(s10,s10), w11=pk2(s11,s11), w12=pk2(s12,s12);
        #pragma unroll
        for(int p=0;p<9;p++){
            ull e0=pk2(F[p].x,  F[p].y);
            ull od=pk2(F[p].y,  F[p+1].x);
            ull e1=pk2(F[p+1].x,F[p+1].y);
            A0[p]=fma2(e0,w00,A0[p]);
            A0[p]=fma2(od,w01,A0[p]);
            A0[p]=fma2(e1,w02,A0[p]);
            A1[p]=fma2(e0,w10,A1[p]);
            A1[p]=fma2(od,w11,A1[p]);
            A1[p]=fma2(e1,w12,A1[p]);
        }
    }

    float b0=bias[lane], b1=bias[lane+32];
    float g0=0.f,g1=0.f,bb0=0.f,bb1=0.f;
    if(ACT==1){ g0=ga[lane]; g1=ga[lane+32]; bb0=be[lane]; bb1=be[lane+32]; }

    #pragma unroll
    for(int p=0;p<9;p++){
        float v0,v1,u0,u1;
        upk2(v0,v1,A0[p]);
        upk2(u0,u1,A1[p]);
        int col=cb+2*p;
        #pragma unroll
        for(int q=0;q<2;q++){
            float vA=(q==0)?v0:v1, vB=(q==0)?u0:u1;
            int cc=col+q;
            int g=l0-9+cc;
            bool inr=(g>=0)&&(g<Ln);
            int a0=lane*SW+cc, a1=(lane+32)*SW+cc;
            if(ACT==0){
                dst[a0]=inr?geluf(vA+b0):0.f;
                dst[a1]=inr?geluf(vB+b1):0.f;
            }else{
                float y0=dst[a0], y1=dst[a1];
                float m0=fmaf(vA+b0,g0,bb0);
                float m1=fmaf(vB+b1,g1,bb1);
                dst[a0]=inr?(siluf(m0)-0.1f*y0):0.f;
                dst[a1]=inr?(siluf(m1)-0.1f*y1):0.f;
            }
        }
    }
}

/* fused RK4 step (256 threads, acc in regs); j==3 adds e_out */
__global__ void __launch_bounds__(256,2) k_rk(
    const float* __restrict__ yIn, float* __restrict__ yOut,
    const float* __restrict__ b1All, const float* __restrict__ b2All, int j)
{
    extern __shared__ float smx[];
    float* A  = smx;
    float* Bf = smx + 64*SW;
    __shared__ float redE[8];
    int t=threadIdx.x, lane=t&31, w=t>>5;
    int slab=blockIdx.y, lvl=slab>>3;
    size_t soff=(size_t)slab*(Cn*Ln);
    int l0=blockIdx.x*TLX;
    int cb=1+18*w;

    float dt=g_dt[lvl*4+j];
    const float* w1T=g_w1T+lvl*12288;
    const float* w2T=g_w2T+lvl*12288;
    const float* bias1=b1All+lvl*64;
    const float* bias2=b2All+lvl*64;
    const float* yS=yIn+soff;

    float acc[32];
    #pragma unroll
    for(int i=0;i<32;i++) acc[i]=0.f;

    for(int idx=t; idx<64*BW; idx+=256){
        int c=idx/BW, b=idx-c*BW;
        int g=l0-9+b;
        A[c*SW+b]=(g>=0&&g<Ln)? yS[(size_t)c*Ln+g] : 0.f;
    }
    for(int idx=t; idx<128; idx+=256){
        int c=idx>>1, col=(idx&1)?(BW-1):0;
        Bf[c*SW+col]=0.f;
    }
    __syncthreads();

    for(int ev=0; ev<4; ev++){
        float* inB=(ev&1)?Bf:A;
        float* hB =(ev&1)?A:Bf;
        float kcoef=(ev==1||ev==2)?2.f:1.f;

        conv_stage<0>(inB,hB,w1T,bias1,(const float*)0,(const float*)0,cb,lane,l0);
        __syncthreads();
        const float* Gp=g_G+((lvl*4+j)*4+ev)*128;
        conv_stage<1>(hB,inB,w2T,bias2,Gp,Gp+64,cb,lane,l0);
        __syncthreads();

        float* kB=inB;
        #pragma unroll
        for(int i=0;i<32;i++){
            int idx=t+i*256;
            int c=idx>>7, l=idx&127;
            acc[i]=fmaf(kcoef,kB[c*SW+l+9],acc[i]);
        }
        if(ev<3){
            float aN=(ev==2)?dt:0.5f*dt;
            for(int idx=t; idx<64*BW; idx+=256){
                int c=idx/BW, b=idx-c*BW;
                int g=l0-9+b;
                float v=0.f;
                if(g>=0&&g<Ln) v=fmaf(aN,kB[c*SW+b],yS[(size_t)c*Ln+g]);
                hB[c*SW+b]=v;
            }
        }
        __syncthreads();
    }

    float s6=dt*(1.f/6.f);
    float esum=0.f;
    #pragma unroll
    for(int i=0;i<32;i++){
        int idx=t+i*256;
        int c=idx>>7, l=idx&127;
        size_t g=soff+(size_t)c*Ln+l0+l;
        float yv=fmaf(s6,acc[i],yIn[g]);
        yOut[g]=yv;
        esum=fmaf(yv,yv,esum);
    }
    if(j==3){
        for(int o=16;o;o>>=1) esum+=__shfl_down_sync(0xffffffffu,esum,o);
        if(lane==0) redE[w]=esum;
        __syncthreads();
        if(t==0){
            float r=0.f;
            for(int i=0;i<8;i++) r+=redE[i];
            atomicAdd(&g_eout[slab],r);
        }
    }
}

__global__ void k_sc(){
    int i=threadIdx.x;
    if(i<32){
        float einm =g_ein[i]*(1.f/(float)(Cn*Ln));
        float eoutm=g_eout[i]*(1.f/(float)(Cn*Ln));
        g_scale[i]=sqrtf(einm/(eoutm+1e-8f));
    }
}

__global__ void __launch_bounds__(256) k_gate(
    const float* __restrict__ cur, const float* __restrict__ bAll,
    const float* __restrict__ det, float* __restrict__ outp, int gi,
    int curBase, int detBase, float* __restrict__ detCopy)
{
    __shared__ float xs[64*130];
    int t=threadIdx.x;
    int slab=blockIdx.y;
    size_t soff=(size_t)slab*(Cn*Ln);
    int l0=blockIdx.x*TLX;
    const float* wT=g_wgT+gi*12288;
    const float* ip=cur+soff;
    float sc=(curBase>=0)?g_scale[curBase+slab]:1.f;
    float sd=(detBase>=0)?g_scale[detBase+slab]:1.f;

    for(int idx=t; idx<64*130; idx+=256){
        int c=idx/130, jj=idx-130*c;
        int gl=l0-1+jj;
        xs[idx]=(gl>=0&&gl<Ln)? ip[(size_t)c*Ln+gl]*sc : 0.f;
    }
    __syncthreads();

    int lane=t&31, w=t>>5;
    int base=w*16;
    float acc0[16],acc1[16];
    #pragma unroll
    for(int i=0;i<16;i++){acc0[i]=0.f;acc1[i]=0.f;}

    for(int c=0;c<64;c++){
        float xv[18];
        #pragma unroll
        for(int i2=0;i2<18;i2++) xv[i2]=xs[c*130+base+i2];
        const float* wp=wT+c*192;
        float w00=__ldg(wp+lane),     w01=__ldg(wp+64+lane),  w02=__ldg(wp+128+lane);
        float w10=__ldg(wp+32+lane),  w11=__ldg(wp+96+lane),  w12=__ldg(wp+160+lane);
        #pragma unroll
        for(int i2=0;i2<16;i2++){
            acc0[i2]=fmaf(xv[i2],w00,fmaf(xv[i2+1],w01,fmaf(xv[i2+2],w02,acc0[i2])));
            acc1[i2]=fmaf(xv[i2],w10,fmaf(xv[i2+1],w11,fmaf(xv[i2+2],w12,acc1[i2])));
        }
    }
    __syncthreads();
    #pragma unroll
    for(int i2=0;i2<16;i2++){
        xs[lane*130+base+i2]=acc0[i2];
        xs[(lane+32)*130+base+i2]=acc1[i2];
    }
    __syncthreads();

    const float* bptr=bAll+gi*64;
    for(int idx=t; idx<64*TLX; idx+=256){
        int c=idx>>7, l=idx&127;
        float v=xs[c*130+l]+bptr[c];
        size_t g=soff+(size_t)c*Ln+l0+l;
        float gt=sigmf(v);
        float dv=det[g]*sd;
        outp[g]=fmaf(gt,dv,cur[g]*sc);
        if(detCopy) detCopy[g]=dv;
    }
}

__global__ void k_attn(const float* __restrict__ cur, const float* __restrict__ det,
                       float* __restrict__ out, const float* __restrict__ w1,
                       const float* __restrict__ b1, const float* __restrict__ w2,
                       const float* __restrict__ b2, int detBase){
    int b=blockIdx.y;
    int l=blockIdx.x*128+threadIdx.x;
    size_t base=(size_t)b*(Cn*Ln)+l;
    float sd=g_scale[detBase+b];
    float h[16];
    #pragma unroll
    for(int i=0;i<16;i++) h[i]=b1[i];
    for(int c=0;c<64;c++){
        float v=cur[base+(size_t)c*Ln];
        #pragma unroll
        for(int i=0;i<16;i++) h[i]=fmaf(v,__ldg(w1+i*64+c),h[i]);
    }
    #pragma unroll
    for(int i=0;i<16;i++) h[i]=geluf(h[i]);
    for(int o=0;o<64;o++){
        float s=b2[o];
        #pragma unroll
        for(int i=0;i<16;i++) s=fmaf(h[i],__ldg(w2+o*16+i),s);
        float a=sigmf(s);
        size_t g=base+(size_t)o*Ln;
        out[g]=det[g]*sd*(1.f+a);
    }
}

extern "C" void kernel_launch(void* const* d_in, const int* in_sizes, int n_in,
                              void* d_out, int out_size){
    const float* x       =(const float*)d_in[0];
    const float* dy_w1   =(const float*)d_in[1];
    const float* dy_b1   =(const float*)d_in[2];
    const float* dy_wg1  =(const float*)d_in[3];
    const float* dy_bg1  =(const float*)d_in[4];
    const float* dy_wg2  =(const float*)d_in[5];
    const float* dy_bg2  =(const float*)d_in[6];
    const float* ode_c1w =(const float*)d_in[7];
    const float* ode_c1b =(const float*)d_in[8];
    const float* ode_c2w =(const float*)d_in[9];
    const float* ode_c2b =(const float*)d_in[10];
    const float* ode_wt  =(const float*)d_in[11];
    const float* ode_bt  =(const float*)d_in[12];
    const float* ode_wm  =(const float*)d_in[13];
    const float* ode_bm  =(const float*)d_in[14];
    const float* ode_emb =(const float*)d_in[15];
    const float* gate_w  =(const float*)d_in[16];
    const float* gate_b  =(const float*)d_in[17];
    const float* attn1_w =(const float*)d_in[18];
    const float* attn1_b =(const float*)d_in[19];
    const float* attn2_w =(const float*)d_in[20];
    const float* attn2_b =(const float*)d_in[21];
    float* out=(float*)d_out;

    void *vp;
    cudaGetSymbolAddress(&vp,g_coef);  float* pCoef=(float*)vp;
    cudaGetSymbolAddress(&vp,g_y);     float* pY   =(float*)vp;
    cudaGetSymbolAddress(&vp,g_y2);    float* pY2  =(float*)vp;
    cudaGetSymbolAddress(&vp,g_bufA);  float* pA   =(float*)vp;
    cudaGetSymbolAddress(&vp,g_bufB);  float* pB   =(float*)vp;
    cudaGetSymbolAddress(&vp,g_dummy); float* pDum =(float*)vp;

    float* orthoPtr=(out_size>NT)?(out+NT):pDum;

    const int shz = 2*64*SW*(int)sizeof(float);   /* 75776 B */
    cudaFuncSetAttribute(k_rk, cudaFuncAttributeMaxDynamicSharedMemorySize, shz);

    k_reset<<<1,32>>>();
    k_wprep<<<192,256>>>(ode_c1w,ode_c2w,gate_w,dy_w1,dy_wg1,dy_wg2,ode_wm);
    k_stat<<<512,256>>>(x);
    k_dywan<<<1,256>>>(dy_b1,dy_bg1,dy_bg2,orthoPtr);
    k_wfilt<<<512,256>>>(x,  pA, pCoef+1*SL, (float*)0, pY+1*SL, 1);
    k_dywan<<<1,256>>>(dy_b1,dy_bg1,dy_bg2,orthoPtr);
    k_wfilt<<<512,256>>>(pA, pB, pCoef+2*SL, (float*)0, pY+2*SL, 1);
    k_dywan<<<1,256>>>(dy_b1,dy_bg1,dy_bg2,orthoPtr);
    k_wfilt<<<512,256>>>(pB, pCoef, pCoef+3*SL, pY, pY+3*SL, 0);

    k_tgrid<<<dim3(512,4),256>>>();
    k_ts<<<1,32>>>();
    k_modtab<<<1,256>>>(ode_wt,ode_bt,ode_bm,ode_emb);

    /* fused RK4: y ping-pongs y <-> y2, ends in y; j=3 accumulates e_out */
    k_rk<<<dim3(16,32),256,shz>>>(pY,  pY2, ode_c1b, ode_c2b, 0);
    k_rk<<<dim3(16,32),256,shz>>>(pY2, pY,  ode_c1b, ode_c2b, 1);
    k_rk<<<dim3(16,32),256,shz>>>(pY,  pY2, ode_c1b, ode_c2b, 2);
    k_rk<<<dim3(16,32),256,shz>>>(pY2, pY,  ode_c1b, ode_c2b, 3);

    k_sc<<<1,32>>>();

    k_gate<<<dim3(16,8),256>>>(pY, gate_b, pY+3*SL, pA, 2, 0, 24, out+3*SL);
    k_attn<<<dim3(16,8),128>>>(pA, pY+2*SL, out+2*SL,
                               attn1_w+1024, attn1_b+16, attn2_w+1024, attn2_b+64, 16);
    k_gate<<<dim3(16,8),256>>>(pA, gate_b, out+2*SL, pB, 1, -1, -1, (float*)0);
    k_attn<<<dim3(16,8),128>>>(pB, pY+1*SL, out+1*SL,
                               attn1_w, attn1_b, attn2_w, attn2_b, 8);
    k_gate<<<dim3(16,8),256>>>(pB, gate_b, out+1*SL, out, 0, -1, -1, (float*)0);
}